// round 15
// baseline (speedup 1.0000x reference)
#include <cuda_runtime.h>

#define B_   4
#define N_   4096
#define DIN  128
#define DH   64
#define DO   128
#define TM   128
#define TN   128
#define NT   (N_/TN)       // 32
#define NW   (N_/32)       // 128 mask words per row
#define LOG2E 1.4426950408889634f
#define EXPC  92.33248261689366f   /* 64 * log2(e) */

// ---------------- scratch ----------------
__device__ __align__(16) unsigned g_adjbits[N_*NW];
// pre-split, pre-swizzled bf16 images. Q/K: per (b,t) 128x64 bf16 (16KB).
// V: per (b,t) transposed 128(dout)x128(key) bf16 (32KB), 256B rows.
__device__ __align__(16) unsigned short g_Q1[B_*NT*8192];
__device__ __align__(16) unsigned short g_Q2[B_*NT*8192];
__device__ __align__(16) unsigned short g_K1[B_*NT*8192];
__device__ __align__(16) unsigned short g_K2[B_*NT*8192];
__device__ __align__(16) unsigned short g_V1[B_*NT*16384];
__device__ __align__(16) unsigned short g_V2[B_*NT*16384];

// ---------------- helpers ----------------
__device__ __forceinline__ unsigned smem_u32(const void* p) {
    unsigned a;
    asm("{ .reg .u64 t; cvta.to.shared.u64 t, %1; cvt.u32.u64 %0, t; }" : "=r"(a) : "l"(p));
    return a;
}
__device__ __forceinline__ float ex2f(float x) {
    float r; asm("ex2.approx.ftz.f32 %0, %1;" : "=f"(r) : "f"(x)); return r;
}
// split (a,b) into bf16x2 hi-part w1 and bf16x2 residual w2 (lo=a, hi=b)
__device__ __forceinline__ void split2(float a, float b, unsigned &w1, unsigned &w2) {
    unsigned hb;
    asm("cvt.rn.bf16x2.f32 %0, %1, %2;" : "=r"(hb) : "f"(b), "f"(a));
    float fa = __uint_as_float(hb << 16);
    float fb = __uint_as_float(hb & 0xffff0000u);
    asm("cvt.rn.bf16x2.f32 %0, %1, %2;" : "=r"(w2) : "f"(b - fb), "f"(a - fa));
    w1 = hb;
}
__device__ __forceinline__ float2 ffma2(float2 a, float2 b, float2 c) {
    unsigned long long ua = *reinterpret_cast<unsigned long long*>(&a);
    unsigned long long ub = *reinterpret_cast<unsigned long long*>(&b);
    unsigned long long uc = *reinterpret_cast<unsigned long long*>(&c);
    unsigned long long ud;
    asm("fma.rn.f32x2 %0, %1, %2, %3;" : "=l"(ud) : "l"(ua), "l"(ub), "l"(uc));
    return *reinterpret_cast<float2*>(&ud);
}
__device__ __forceinline__ void ldsm4(unsigned* r, unsigned addr) {
    asm volatile("ldmatrix.sync.aligned.m8n8.x4.shared.b16 {%0,%1,%2,%3}, [%4];"
        : "=r"(r[0]), "=r"(r[1]), "=r"(r[2]), "=r"(r[3]) : "r"(addr));
}
__device__ __forceinline__ void mma16816(float* c, unsigned a0, unsigned a1,
                                         unsigned a2, unsigned a3,
                                         unsigned b0, unsigned b1) {
    asm volatile("mma.sync.aligned.m16n8k16.row.col.f32.bf16.bf16.f32 "
        "{%0,%1,%2,%3}, {%4,%5,%6,%7}, {%8,%9}, {%0,%1,%2,%3};"
        : "+f"(c[0]), "+f"(c[1]), "+f"(c[2]), "+f"(c[3])
        : "r"(a0), "r"(a1), "r"(a2), "r"(a3), "r"(b0), "r"(b1));
}
#define CP_COMMIT asm volatile("cp.async.commit_group;" ::: "memory")
#define CP_WAIT1  asm volatile("cp.async.wait_group 1;" ::: "memory")
__device__ __forceinline__ void cpa16(unsigned dst, const void* src) {
    asm volatile("cp.async.cg.shared.global [%0], [%1], 16;" :: "r"(dst), "l"(src) : "memory");
}
__device__ __forceinline__ void cpcopy(unsigned sdst, const char* gsrc, int nbytes, int tid) {
    for (int i = tid*16; i < nbytes; i += 256*16) cpa16(sdst + i, gsrc + i);
}

// ---------------- kernel 1: fused projections + split/swizzle pack ----------------
// grid (NT, B_, 4), 256 threads, 4 CTAs per SM. CTA (t,b,qtr): 32 rows of tile t.
// Each thread: 2 adjacent output cols x 16 rows -> per k: 4 LDS.128 + 1 LDG.64 + 16 FFMA2.
// smem: hT [DIN k][32 rows + pad] fp32 (18KB), stage [256 cols][33] fp32 (33KB).
#define HT_ST 36
#define ST_ST 33
#define PP_SMEM (DIN*HT_ST*4 + 256*ST_ST*4)   /* 18432 + 33792 = 52224 B */

__global__ void __launch_bounds__(256, 4)
gat_proj_pack(const float* __restrict__ h,
              const float* __restrict__ Ws,
              const float* __restrict__ Wt,
              const float* __restrict__ Wc) {
    extern __shared__ float sm[];
    float* hT    = sm;                      // [k][r] r in 0..31 (this quarter)
    float* stage = sm + DIN*HT_ST;
    const int t = blockIdx.x, b = blockIdx.y, qtr = blockIdx.z;
    const int tid = threadIdx.x;
    const int r0p = 32*qtr;
    const size_t nb = (size_t)b*N_ + (size_t)t*128 + r0p;   // first row of this quarter

    char* qb1 = (char*)(g_Q1 + ((size_t)b*NT + t)*8192);
    char* qb2 = (char*)(g_Q2 + ((size_t)b*NT + t)*8192);
    char* kb1 = (char*)(g_K1 + ((size_t)b*NT + t)*8192);
    char* kb2 = (char*)(g_K2 + ((size_t)b*NT + t)*8192);
    char* vb1 = (char*)(g_V1 + ((size_t)b*NT + t)*16384);
    char* vb2 = (char*)(g_V2 + ((size_t)b*NT + t)*16384);

    // load 32 rows of h transposed: hT[k][r]
    for (int idx = tid; idx < 1024; idx += 256) {
        int r = idx & 31, k4 = idx >> 5;
        float4 v = *(const float4*)(h + (nb + r)*DIN + 4*k4);
        hT[(4*k4+0)*HT_ST + r] = v.x;
        hT[(4*k4+1)*HT_ST + r] = v.y;
        hT[(4*k4+2)*HT_ST + r] = v.z;
        hT[(4*k4+3)*HT_ST + r] = v.w;
    }
    __syncthreads();

    // thread -> (2 cols, 16 rows): cg = tid & 127 col pair, rg = tid >> 7 row half
    const int cg = tid & 127, rg = tid >> 7;
    const int rbase = rg * 16;
    const float* Wp; int wstride, c0;
    if (cg < 32)       { Wp = Ws; wstride = DH; c0 = 2*cg; }
    else if (cg < 64)  { Wp = Wt; wstride = DH; c0 = 2*cg - 64; }
    else               { Wp = Wc; wstride = DO; c0 = 2*(cg - 64); }

    float2 accA[8], accB[8];                // col c0 / col c0+1, 16 rows each
#pragma unroll
    for (int q = 0; q < 8; q++) { accA[q] = make_float2(0.f, 0.f); accB[q] = make_float2(0.f, 0.f); }
#pragma unroll 4
    for (int k = 0; k < DIN; k++) {
        float2 w2 = *(const float2*)(Wp + k*wstride + c0);
        float2 wa = make_float2(w2.x, w2.x);
        float2 wb = make_float2(w2.y, w2.y);
        const float4* hp4 = (const float4*)(hT + k*HT_ST + rbase);
#pragma unroll
        for (int q = 0; q < 4; q++) {       // 4 LDS.128 : 16 FFMA2
            float4 h4 = hp4[q];
            float2 hlo = make_float2(h4.x, h4.y);
            float2 hhi = make_float2(h4.z, h4.w);
            accA[2*q]   = ffma2(wa, hlo, accA[2*q]);
            accA[2*q+1] = ffma2(wa, hhi, accA[2*q+1]);
            accB[2*q]   = ffma2(wb, hlo, accB[2*q]);
            accB[2*q+1] = ffma2(wb, hhi, accB[2*q+1]);
        }
    }
    // stage[col][row] col-major, col stride 33
    {
        float* sA = stage + (2*cg)*ST_ST + rbase;
        float* sB = stage + (2*cg + 1)*ST_ST + rbase;
#pragma unroll
        for (int q = 0; q < 8; q++) {
            sA[2*q] = accA[q].x; sA[2*q+1] = accA[q].y;
            sB[2*q] = accB[q].x; sB[2*q+1] = accB[q].y;
        }
    }
    __syncthreads();

    // Q/K images, rows r0p..r0p+31  (stage cols 0..63 = Whs, 64..127 = Wht)
    for (int i = tid; i < 256; i += 256) {
        int r = i >> 3, s = i & 7;
        int rr = r0p + r;
        int off = rr*128 + ((s ^ (rr & 7)) << 4);
        uint4 u1, u2;
        {
            const float* sc = stage + (8*s)*ST_ST + r;
            split2(sc[0*ST_ST], sc[1*ST_ST], u1.x, u2.x);
            split2(sc[2*ST_ST], sc[3*ST_ST], u1.y, u2.y);
            split2(sc[4*ST_ST], sc[5*ST_ST], u1.z, u2.z);
            split2(sc[6*ST_ST], sc[7*ST_ST], u1.w, u2.w);
            *(uint4*)(qb1 + off) = u1; *(uint4*)(qb2 + off) = u2;
        }
        {
            const float* sc = stage + (64 + 8*s)*ST_ST + r;
            split2(sc[0*ST_ST], sc[1*ST_ST], u1.x, u2.x);
            split2(sc[2*ST_ST], sc[3*ST_ST], u1.y, u2.y);
            split2(sc[4*ST_ST], sc[5*ST_ST], u1.z, u2.z);
            split2(sc[6*ST_ST], sc[7*ST_ST], u1.w, u2.w);
            *(uint4*)(kb1 + off) = u1; *(uint4*)(kb2 + off) = u2;
        }
    }
    // V image (transposed [dout][key]): this quarter covers keys r0p..r0p+31
    for (int i = tid; i < 512; i += 256) {
        int d = i & 127, sh = i >> 7;            // sh 0..3 -> 8 keys each
        int sg = (r0p >> 3) + sh;                // global 16B segment 0..15
        const float* sc = stage + (128 + d)*ST_ST + 8*sh;
        uint4 u1, u2;
        split2(sc[0], sc[1], u1.x, u2.x);
        split2(sc[2], sc[3], u1.y, u2.y);
        split2(sc[4], sc[5], u1.z, u2.z);
        split2(sc[6], sc[7], u1.w, u2.w);
        int off = d*256 + ((sg ^ (d & 7)) << 4);
        *(uint4*)(vb1 + off) = u1; *(uint4*)(vb2 + off) = u2;
    }
}

// ---------------- kernel 2: adjacency bitmask (standalone, 4096 blocks) ----------
__global__ void gat_pack_adj_kernel(const int* __restrict__ adj) {
    const int row = blockIdx.x, wi = threadIdx.x >> 5, lane = threadIdx.x & 31;
#pragma unroll 4
    for (int w = 0; w < 32; w++) {
        int word = wi*32 + w, col = word*32 + lane;
        unsigned bit = (adj[(size_t)row*N_ + col] > 0) ? 1u : 0u;
        unsigned m = __ballot_sync(0xffffffffu, bit);
        if (lane == 0) g_adjbits[row*NW + word] = m;
    }
}

// ---------------- kernel 3: HMMA split-precision flash attention ----------------
// smem: Q 32KB | K bufs 2x32KB | V bufs 2x64KB  = 229376 B
#define SOFF_K 32768
#define SOFF_V 98304
#define SMEM_TOT 229376

__global__ void __launch_bounds__(256, 1)
gat_attn_kernel(float* __restrict__ out) {
    extern __shared__ char smc[];
    const unsigned sb = smem_u32(smc);
    const int qt = blockIdx.x, b = blockIdx.y;
    const int tid = threadIdx.x, lane = tid & 31, wid = tid >> 5;
    const int r0 = wid * 16;

    // ldmatrix lane geometry
    const unsigned q_row  = r0 + (lane & 15);
    const unsigned q_sel  = lane >> 4;
    const unsigned q_x7   = q_row & 7;
    const unsigned kv_r   = (lane & 7) | ((lane & 16) >> 1);   // 0..15
    const unsigned kv_sel = (lane >> 3) & 1;
    const unsigned kv_x7  = kv_r & 7;
    const unsigned sQrow  = sb + q_row*128;

    // ---- prologue async loads: group0 = Q + K(0) + V(0); group1 = K(1) + V(1)
    const size_t qoff = ((size_t)b*NT + qt)*8192;
    cpcopy(sb,          (const char*)(g_Q1 + qoff), 16384, tid);
    cpcopy(sb + 16384,  (const char*)(g_Q2 + qoff), 16384, tid);
    {
        size_t k0 = ((size_t)b*NT + 0);
        cpcopy(sb + SOFF_K,          (const char*)(g_K1 + k0*8192),  16384, tid);
        cpcopy(sb + SOFF_K + 16384,  (const char*)(g_K2 + k0*8192),  16384, tid);
        cpcopy(sb + SOFF_V,          (const char*)(g_V1 + k0*16384), 32768, tid);
        cpcopy(sb + SOFF_V + 32768,  (const char*)(g_V2 + k0*16384), 32768, tid);
    }
    CP_COMMIT;
    {
        size_t k1 = ((size_t)b*NT + 1);
        cpcopy(sb + SOFF_K + 32768,  (const char*)(g_K1 + k1*8192),  16384, tid);
        cpcopy(sb + SOFF_K + 49152,  (const char*)(g_K2 + k1*8192),  16384, tid);
        cpcopy(sb + SOFF_V + 65536,  (const char*)(g_V1 + k1*16384), 32768, tid);
        cpcopy(sb + SOFF_V + 98304,  (const char*)(g_V2 + k1*16384), 32768, tid);
    }
    CP_COMMIT;

    float o[16][4];
#pragma unroll
    for (int j = 0; j < 16; j++)
#pragma unroll
        for (int q = 0; q < 4; q++) o[j][q] = 0.f;
    float lA = 0.f, lB = 0.f;

    const int rAg = qt*128 + r0 + (lane >> 2);   // global query row for c0,c1
    const unsigned* adjA = g_adjbits + (size_t)rAg*NW;
    const unsigned* adjB = g_adjbits + (size_t)(rAg + 8)*NW;

    for (int t = 0; t < NT; t++) {
        CP_WAIT1;
        __syncthreads();
        const unsigned kb = sb + SOFF_K + (t & 1)*32768;
        const unsigned vb = sb + SOFF_V + (t & 1)*65536;

        float s[16][4];
#pragma unroll
        for (int j = 0; j < 16; j++)
#pragma unroll
            for (int q = 0; q < 4; q++) s[j][q] = 0.f;

        unsigned mA0 = adjA[t*4+0], mA1 = adjA[t*4+1], mA2 = adjA[t*4+2], mA3 = adjA[t*4+3];
        unsigned mB0 = adjB[t*4+0], mB1 = adjB[t*4+1], mB2 = adjB[t*4+2], mB3 = adjB[t*4+3];
        unsigned p1lo[16], p1hi[16], p2lo[16], p2hi[16];

        // softmax for one n8-chunk j: mask + exp + bf16 split
        auto softmax_j = [&](int j) {
            unsigned wa = (j < 4) ? mA0 : (j < 8) ? mA1 : (j < 12) ? mA2 : mA3;
            unsigned wb = (j < 4) ? mB0 : (j < 8) ? mB1 : (j < 12) ? mB2 : mB3;
            int bp = 8*(j & 3) + 2*(lane & 3);
            float pa0 = ((wa >> bp)     & 1u) ? ex2f(fmaf(s[j][0], LOG2E, -EXPC)) : 0.f;
            float pa1 = ((wa >> (bp+1)) & 1u) ? ex2f(fmaf(s[j][1], LOG2E, -EXPC)) : 0.f;
            float pb0 = ((wb >> bp)     & 1u) ? ex2f(fmaf(s[j][2], LOG2E, -EXPC)) : 0.f;
            float pb1 = ((wb >> (bp+1)) & 1u) ? ex2f(fmaf(s[j][3], LOG2E, -EXPC)) : 0.f;
            lA += pa0 + pa1;
            lB += pb0 + pb1;
            split2(pa0, pa1, p1lo[j], p2lo[j]);
            split2(pb0, pb1, p1hi[j], p2hi[j]);
        };
        // PV body for one 16-key chunk kk
        auto pv_kk = [&](int kk) {
            unsigned vx = ((2*kk + kv_sel) ^ kv_x7) << 4;
            unsigned a10 = p1lo[2*kk], a11 = p1hi[2*kk], a12 = p1lo[2*kk+1], a13 = p1hi[2*kk+1];
            unsigned a20 = p2lo[2*kk], a21 = p2hi[2*kk], a22 = p2lo[2*kk+1], a23 = p2hi[2*kk+1];
#pragma unroll
            for (int jp = 0; jp < 8; jp++) {
                unsigned bf[4];
                unsigned va = vb + kv_r*256 + jp*4096 + vx;
                ldsm4(bf, va);                        // V1 (rows = dout, pre-transposed)
                mma16816(o[2*jp],   a10,a11,a12,a13, bf[0],bf[1]);
                mma16816(o[2*jp+1], a10,a11,a12,a13, bf[2],bf[3]);
                mma16816(o[2*jp],   a20,a21,a22,a23, bf[0],bf[1]);
                mma16816(o[2*jp+1], a20,a21,a22,a23, bf[2],bf[3]);
                ldsm4(bf, va + 32768);                // V2
                mma16816(o[2*jp],   a10,a11,a12,a13, bf[0],bf[1]);
                mma16816(o[2*jp+1], a10,a11,a12,a13, bf[2],bf[3]);
            }
        };

        // ---- QK half 0: key chunks jp 0..3 (all dh) ----
#pragma unroll
        for (int kk = 0; kk < 4; kk++) {
            unsigned a1[4], a2[4];
            unsigned qx = ((2*kk + q_sel) ^ q_x7) << 4;
            ldsm4(a1, sQrow + qx);
            ldsm4(a2, sQrow + 16384 + qx);
            unsigned kx = ((2*kk + kv_sel) ^ kv_x7) << 4;
#pragma unroll
            for (int jp = 0; jp < 4; jp++) {
                unsigned bf[4];
                unsigned ka = kb + kv_r*128 + jp*2048 + kx;
                ldsm4(bf, ka);                        // K1
                mma16816(s[2*jp],   a1[0],a1[1],a1[2],a1[3], bf[0],bf[1]);
                mma16816(s[2*jp+1], a1[0],a1[1],a1[2],a1[3], bf[2],bf[3]);
                mma16816(s[2*jp],   a2[0],a2[1],a2[2],a2[3], bf[0],bf[1]);
                mma16816(s[2*jp+1], a2[0],a2[1],a2[2],a2[3], bf[2],bf[3]);
                ldsm4(bf, ka + 16384);                // K2
                mma16816(s[2*jp],   a1[0],a1[1],a1[2],a1[3], bf[0],bf[1]);
                mma16816(s[2*jp+1], a1[0],a1[1],a1[2],a1[3], bf[2],bf[3]);
            }
        }
        // ---- QK half 1 (jp 4..7) interleaved with softmax of half 0 ----
#pragma unroll
        for (int kk = 0; kk < 4; kk++) {
            unsigned a1[4], a2[4];
            unsigned qx = ((2*kk + q_sel) ^ q_x7) << 4;
            ldsm4(a1, sQrow + qx);
            ldsm4(a2, sQrow + 16384 + qx);
            unsigned kx = ((2*kk + kv_sel) ^ kv_x7) << 4;
#pragma unroll
            for (int jp = 4; jp < 8; jp++) {
                unsigned bf[4];
                unsigned ka = kb + kv_r*128 + jp*2048 + kx;
                ldsm4(bf, ka);
                mma16816(s[2*jp],   a1[0],a1[1],a1[2],a1[3], bf[0],bf[1]);
                mma16816(s[2*jp+1], a1[0],a1[1],a1[2],a1[3], bf[2],bf[3]);
                mma16816(s[2*jp],   a2[0],a2[1],a2[2],a2[3], bf[0],bf[1]);
                mma16816(s[2*jp+1], a2[0],a2[1],a2[2],a2[3], bf[2],bf[3]);
                ldsm4(bf, ka + 16384);
                mma16816(s[2*jp],   a1[0],a1[1],a1[2],a1[3], bf[0],bf[1]);
                mma16816(s[2*jp+1], a1[0],a1[1],a1[2],a1[3], bf[2],bf[3]);
            }
            softmax_j(2*kk);
            softmax_j(2*kk + 1);
        }
        // ---- PV half 0 (keys 0..63) interleaved with softmax of half 1 ----
#pragma unroll
        for (int kk = 0; kk < 4; kk++) {
            softmax_j(8 + 2*kk);
            softmax_j(9 + 2*kk);
            pv_kk(kk);
        }
        // ---- PV half 1 (keys 64..127) ----
#pragma unroll
        for (int kk = 4; kk < 8; kk++) pv_kk(kk);

        __syncthreads();   // everyone done reading buf (t&1) before overwrite
        if (t + 2 < NT) {
            size_t kx = ((size_t)b*NT + t + 2);
            unsigned kd = sb + SOFF_K + (t & 1)*32768;
            unsigned vd = sb + SOFF_V + (t & 1)*65536;
            cpcopy(kd,          (const char*)(g_K1 + kx*8192),  16384, tid);
            cpcopy(kd + 16384,  (const char*)(g_K2 + kx*8192),  16384, tid);
            cpcopy(vd,          (const char*)(g_V1 + kx*16384), 32768, tid);
            cpcopy(vd + 32768,  (const char*)(g_V2 + kx*16384), 32768, tid);
        }
        CP_COMMIT;
    }

    // ---- epilogue: quad-reduce l, normalize, store ----
    lA += __shfl_xor_sync(0xffffffffu, lA, 1);
    lA += __shfl_xor_sync(0xffffffffu, lA, 2);
    lB += __shfl_xor_sync(0xffffffffu, lB, 1);
    lB += __shfl_xor_sync(0xffffffffu, lB, 2);
    float invA = 1.f / lA, invB = 1.f / lB;

    float* outA = out + ((size_t)b*N_ + rAg)*DO + 2*(lane & 3);
    float* outB = outA + 8*DO;
#pragma unroll
    for (int j = 0; j < 16; j++) {
        *(float2*)(outA + 8*j) = make_float2(o[j][0]*invA, o[j][1]*invA);
        *(float2*)(outB + 8*j) = make_float2(o[j][2]*invB, o[j][3]*invB);
    }
}

// ---------------- launch ----------------
extern "C" void kernel_launch(void* const* d_in, const int* in_sizes, int n_in,
                              void* d_out, int out_size) {
    const float* h   = (const float*)d_in[0];
    const int*   adj = (const int*)  d_in[1];
    const float* Ws  = (const float*)d_in[2];
    const float* Wt  = (const float*)d_in[3];
    const float* Wc  = (const float*)d_in[4];
    float* out = (float*)d_out;

    cudaFuncSetAttribute(gat_proj_pack,
                         cudaFuncAttributeMaxDynamicSharedMemorySize, PP_SMEM);
    cudaFuncSetAttribute(gat_attn_kernel,
                         cudaFuncAttributeMaxDynamicSharedMemorySize, SMEM_TOT);

    // fork a non-blocking stream so the DRAM-bound adjacency pack overlaps the
    // latency-bound projection kernel. Event fork/join is graph-capturable.
    cudaStream_t s2;
    cudaEvent_t evFork, evJoin;
    cudaStreamCreateWithFlags(&s2, cudaStreamNonBlocking);
    cudaEventCreateWithFlags(&evFork, cudaEventDisableTiming);
    cudaEventCreateWithFlags(&evJoin, cudaEventDisableTiming);

    cudaEventRecord(evFork, 0);
    cudaStreamWaitEvent(s2, evFork, 0);

    gat_proj_pack<<<dim3(NT, B_, 4), 256, PP_SMEM>>>(h, Ws, Wt, Wc);   // stream 0
    gat_pack_adj_kernel<<<N_, 128, 0, s2>>>(adj);                      // stream s2

    cudaEventRecord(evJoin, s2);
    cudaStreamWaitEvent(0, evJoin, 0);

    gat_attn_kernel<<<dim3(N_/TM, B_), 256, SMEM_TOT>>>(out);          // stream 0

    cudaEventDestroy(evFork);
    cudaEventDestroy(evJoin);
    cudaStreamDestroy(s2);
}

// round 16
// speedup vs baseline: 1.0365x; 1.0365x over previous
#include <cuda_runtime.h>

#define B_   4
#define N_   4096
#define DIN  128
#define DH   64
#define DO   128
#define TM   128
#define TN   128
#define NT   (N_/TN)       // 32
#define NW   (N_/32)       // 128 mask words per row
#define LOG2E 1.4426950408889634f
#define EXPC  92.33248261689366f   /* 64 * log2(e) */

// ---------------- scratch ----------------
__device__ __align__(16) unsigned g_adjbits[N_*NW];
// pre-split, pre-swizzled bf16 images. Q/K: per (b,t) 128x64 bf16 (16KB).
// V: per (b,t) transposed 128(dout)x128(key) bf16 (32KB), 256B rows.
__device__ __align__(16) unsigned short g_Q1[B_*NT*8192];
__device__ __align__(16) unsigned short g_Q2[B_*NT*8192];
__device__ __align__(16) unsigned short g_K1[B_*NT*8192];
__device__ __align__(16) unsigned short g_K2[B_*NT*8192];
__device__ __align__(16) unsigned short g_V1[B_*NT*16384];
__device__ __align__(16) unsigned short g_V2[B_*NT*16384];

// ---------------- helpers ----------------
__device__ __forceinline__ unsigned smem_u32(const void* p) {
    unsigned a;
    asm("{ .reg .u64 t; cvta.to.shared.u64 t, %1; cvt.u32.u64 %0, t; }" : "=r"(a) : "l"(p));
    return a;
}
__device__ __forceinline__ float ex2f(float x) {
    float r; asm("ex2.approx.ftz.f32 %0, %1;" : "=f"(r) : "f"(x)); return r;
}
// split (a,b) into bf16x2 hi-part w1 and bf16x2 residual w2 (lo=a, hi=b)
__device__ __forceinline__ void split2(float a, float b, unsigned &w1, unsigned &w2) {
    unsigned hb;
    asm("cvt.rn.bf16x2.f32 %0, %1, %2;" : "=r"(hb) : "f"(b), "f"(a));
    float fa = __uint_as_float(hb << 16);
    float fb = __uint_as_float(hb & 0xffff0000u);
    asm("cvt.rn.bf16x2.f32 %0, %1, %2;" : "=r"(w2) : "f"(b - fb), "f"(a - fa));
    w1 = hb;
}
__device__ __forceinline__ float2 ffma2(float2 a, float2 b, float2 c) {
    unsigned long long ua = *reinterpret_cast<unsigned long long*>(&a);
    unsigned long long ub = *reinterpret_cast<unsigned long long*>(&b);
    unsigned long long uc = *reinterpret_cast<unsigned long long*>(&c);
    unsigned long long ud;
    asm("fma.rn.f32x2 %0, %1, %2, %3;" : "=l"(ud) : "l"(ua), "l"(ub), "l"(uc));
    return *reinterpret_cast<float2*>(&ud);
}
__device__ __forceinline__ void ldsm4(unsigned* r, unsigned addr) {
    asm volatile("ldmatrix.sync.aligned.m8n8.x4.shared.b16 {%0,%1,%2,%3}, [%4];"
        : "=r"(r[0]), "=r"(r[1]), "=r"(r[2]), "=r"(r[3]) : "r"(addr));
}
__device__ __forceinline__ void mma16816(float* c, unsigned a0, unsigned a1,
                                         unsigned a2, unsigned a3,
                                         unsigned b0, unsigned b1) {
    asm volatile("mma.sync.aligned.m16n8k16.row.col.f32.bf16.bf16.f32 "
        "{%0,%1,%2,%3}, {%4,%5,%6,%7}, {%8,%9}, {%0,%1,%2,%3};"
        : "+f"(c[0]), "+f"(c[1]), "+f"(c[2]), "+f"(c[3])
        : "r"(a0), "r"(a1), "r"(a2), "r"(a3), "r"(b0), "r"(b1));
}
#define CP_COMMIT asm volatile("cp.async.commit_group;" ::: "memory")
#define CP_WAIT1  asm volatile("cp.async.wait_group 1;" ::: "memory")
__device__ __forceinline__ void cpa16(unsigned dst, const void* src) {
    asm volatile("cp.async.cg.shared.global [%0], [%1], 16;" :: "r"(dst), "l"(src) : "memory");
}
__device__ __forceinline__ void cpcopy(unsigned sdst, const char* gsrc, int nbytes, int tid) {
    for (int i = tid*16; i < nbytes; i += 256*16) cpa16(sdst + i, gsrc + i);
}

// ---------------- kernel 1: fused projections + split/swizzle pack ----------------
// grid (NT, B_, 2), 256 threads, 2 CTAs per SM. CTA (t,b,half): 64 rows of tile t.
// Each thread: 2 adjacent output cols x 32 rows  -> per k: 8 LDS.128 + 1 LDG.64 + 32 FFMA2.
// smem: hT [DIN k][64 rows + pad] fp32, stage [256 cols][65] fp32 col-major.
#define HT_ST 68
#define ST_ST 65
#define PP_SMEM (DIN*HT_ST*4 + 256*ST_ST*4)   /* 34816 + 66560 = 101376 B */

__global__ void __launch_bounds__(256, 2)
gat_proj_pack(const float* __restrict__ h,
              const float* __restrict__ Ws,
              const float* __restrict__ Wt,
              const float* __restrict__ Wc) {
    extern __shared__ float sm[];
    float* hT    = sm;                      // [k][r] r in 0..63 (this half)
    float* stage = sm + DIN*HT_ST;
    const int t = blockIdx.x, b = blockIdx.y, half = blockIdx.z;
    const int tid = threadIdx.x;
    const int r0p = 64*half;
    const size_t nb = (size_t)b*N_ + (size_t)t*128 + r0p;   // first row of this half

    char* qb1 = (char*)(g_Q1 + ((size_t)b*NT + t)*8192);
    char* qb2 = (char*)(g_Q2 + ((size_t)b*NT + t)*8192);
    char* kb1 = (char*)(g_K1 + ((size_t)b*NT + t)*8192);
    char* kb2 = (char*)(g_K2 + ((size_t)b*NT + t)*8192);
    char* vb1 = (char*)(g_V1 + ((size_t)b*NT + t)*16384);
    char* vb2 = (char*)(g_V2 + ((size_t)b*NT + t)*16384);

    // load 64 rows of h transposed: hT[k][r]
    for (int idx = tid; idx < 2048; idx += 256) {
        int r = idx & 63, k4 = idx >> 6;
        float4 v = *(const float4*)(h + (nb + r)*DIN + 4*k4);
        hT[(4*k4+0)*HT_ST + r] = v.x;
        hT[(4*k4+1)*HT_ST + r] = v.y;
        hT[(4*k4+2)*HT_ST + r] = v.z;
        hT[(4*k4+3)*HT_ST + r] = v.w;
    }
    __syncthreads();

    // thread -> (2 cols, 32 rows): cg = tid & 127 selects col pair, rg = tid >> 7 row half
    const int cg = tid & 127, rg = tid >> 7;
    const int rbase = rg * 32;
    const float* Wp; int wstride, c0;
    if (cg < 32)       { Wp = Ws; wstride = DH; c0 = 2*cg; }
    else if (cg < 64)  { Wp = Wt; wstride = DH; c0 = 2*cg - 64; }
    else               { Wp = Wc; wstride = DO; c0 = 2*(cg - 64); }

    float2 accA[16], accB[16];              // col c0 / col c0+1, 32 rows each
#pragma unroll
    for (int q = 0; q < 16; q++) { accA[q] = make_float2(0.f, 0.f); accB[q] = make_float2(0.f, 0.f); }
#pragma unroll 4
    for (int k = 0; k < DIN; k++) {
        float2 w2 = *(const float2*)(Wp + k*wstride + c0);
        float2 wa = make_float2(w2.x, w2.x);
        float2 wb = make_float2(w2.y, w2.y);
        const float4* hp4 = (const float4*)(hT + k*HT_ST + rbase);
#pragma unroll
        for (int q = 0; q < 8; q++) {       // 8 LDS.128 : 32 FFMA2
            float4 h4 = hp4[q];
            float2 hlo = make_float2(h4.x, h4.y);
            float2 hhi = make_float2(h4.z, h4.w);
            accA[2*q]   = ffma2(wa, hlo, accA[2*q]);
            accA[2*q+1] = ffma2(wa, hhi, accA[2*q+1]);
            accB[2*q]   = ffma2(wb, hlo, accB[2*q]);
            accB[2*q+1] = ffma2(wb, hhi, accB[2*q+1]);
        }
    }
    // stage[col][row] col-major, col stride 65
    {
        float* sA = stage + (2*cg)*ST_ST + rbase;
        float* sB = stage + (2*cg + 1)*ST_ST + rbase;
#pragma unroll
        for (int q = 0; q < 16; q++) {
            sA[2*q] = accA[q].x; sA[2*q+1] = accA[q].y;
            sB[2*q] = accB[q].x; sB[2*q+1] = accB[q].y;
        }
    }
    __syncthreads();

    // Q/K images, rows r0p..r0p+63  (stage cols 0..63 = Whs, 64..127 = Wht)
    for (int i = tid; i < 512; i += 256) {
        int r = i >> 3, s = i & 7;
        int rr = r0p + r;
        int off = rr*128 + ((s ^ (rr & 7)) << 4);
        uint4 u1, u2;
        {
            const float* sc = stage + (8*s)*ST_ST + r;
            split2(sc[0*ST_ST], sc[1*ST_ST], u1.x, u2.x);
            split2(sc[2*ST_ST], sc[3*ST_ST], u1.y, u2.y);
            split2(sc[4*ST_ST], sc[5*ST_ST], u1.z, u2.z);
            split2(sc[6*ST_ST], sc[7*ST_ST], u1.w, u2.w);
            *(uint4*)(qb1 + off) = u1; *(uint4*)(qb2 + off) = u2;
        }
        {
            const float* sc = stage + (64 + 8*s)*ST_ST + r;
            split2(sc[0*ST_ST], sc[1*ST_ST], u1.x, u2.x);
            split2(sc[2*ST_ST], sc[3*ST_ST], u1.y, u2.y);
            split2(sc[4*ST_ST], sc[5*ST_ST], u1.z, u2.z);
            split2(sc[6*ST_ST], sc[7*ST_ST], u1.w, u2.w);
            *(uint4*)(kb1 + off) = u1; *(uint4*)(kb2 + off) = u2;
        }
    }
    // V image (transposed [dout][key]): this half covers keys r0p..r0p+63
    for (int i = tid; i < 1024; i += 256) {
        int d = i & 127, sh = i >> 7;            // sh 0..7 -> 8 keys each
        int sg = (r0p >> 3) + sh;                // global 16B segment 0..15
        const float* sc = stage + (128 + d)*ST_ST + 8*sh;
        uint4 u1, u2;
        split2(sc[0], sc[1], u1.x, u2.x);
        split2(sc[2], sc[3], u1.y, u2.y);
        split2(sc[4], sc[5], u1.z, u2.z);
        split2(sc[6], sc[7], u1.w, u2.w);
        int off = d*256 + ((sg ^ (d & 7)) << 4);
        *(uint4*)(vb1 + off) = u1; *(uint4*)(vb2 + off) = u2;
    }
}

// ---------------- kernel 2: adjacency bitmask (standalone, 4096 blocks) ----------
__global__ void gat_pack_adj_kernel(const int* __restrict__ adj) {
    const int row = blockIdx.x, wi = threadIdx.x >> 5, lane = threadIdx.x & 31;
#pragma unroll 4
    for (int w = 0; w < 32; w++) {
        int word = wi*32 + w, col = word*32 + lane;
        unsigned bit = (adj[(size_t)row*N_ + col] > 0) ? 1u : 0u;
        unsigned m = __ballot_sync(0xffffffffu, bit);
        if (lane == 0) g_adjbits[row*NW + word] = m;
    }
}

// ---------------- kernel 3: HMMA split-precision flash attention ----------------
// smem: Q 32KB | K bufs 2x32KB | V bufs 2x64KB  = 229376 B
#define SOFF_K 32768
#define SOFF_V 98304
#define SMEM_TOT 229376

__global__ void __launch_bounds__(256, 1)
gat_attn_kernel(float* __restrict__ out) {
    extern __shared__ char smc[];
    const unsigned sb = smem_u32(smc);
    const int qt = blockIdx.x, b = blockIdx.y;
    const int tid = threadIdx.x, lane = tid & 31, wid = tid >> 5;
    const int r0 = wid * 16;

    // ldmatrix lane geometry
    const unsigned q_row  = r0 + (lane & 15);
    const unsigned q_sel  = lane >> 4;
    const unsigned q_x7   = q_row & 7;
    const unsigned kv_r   = (lane & 7) | ((lane & 16) >> 1);   // 0..15
    const unsigned kv_sel = (lane >> 3) & 1;
    const unsigned kv_x7  = kv_r & 7;
    const unsigned sQrow  = sb + q_row*128;

    // ---- prologue async loads: group0 = Q + K(0) + V(0); group1 = K(1) + V(1)
    const size_t qoff = ((size_t)b*NT + qt)*8192;
    cpcopy(sb,          (const char*)(g_Q1 + qoff), 16384, tid);
    cpcopy(sb + 16384,  (const char*)(g_Q2 + qoff), 16384, tid);
    {
        size_t k0 = ((size_t)b*NT + 0);
        cpcopy(sb + SOFF_K,          (const char*)(g_K1 + k0*8192),  16384, tid);
        cpcopy(sb + SOFF_K + 16384,  (const char*)(g_K2 + k0*8192),  16384, tid);
        cpcopy(sb + SOFF_V,          (const char*)(g_V1 + k0*16384), 32768, tid);
        cpcopy(sb + SOFF_V + 32768,  (const char*)(g_V2 + k0*16384), 32768, tid);
    }
    CP_COMMIT;
    {
        size_t k1 = ((size_t)b*NT + 1);
        cpcopy(sb + SOFF_K + 32768,  (const char*)(g_K1 + k1*8192),  16384, tid);
        cpcopy(sb + SOFF_K + 49152,  (const char*)(g_K2 + k1*8192),  16384, tid);
        cpcopy(sb + SOFF_V + 65536,  (const char*)(g_V1 + k1*16384), 32768, tid);
        cpcopy(sb + SOFF_V + 98304,  (const char*)(g_V2 + k1*16384), 32768, tid);
    }
    CP_COMMIT;

    float o[16][4];
#pragma unroll
    for (int j = 0; j < 16; j++)
#pragma unroll
        for (int q = 0; q < 4; q++) o[j][q] = 0.f;
    float lA = 0.f, lB = 0.f;

    const int rAg = qt*128 + r0 + (lane >> 2);   // global query row for c0,c1
    const unsigned* adjA = g_adjbits + (size_t)rAg*NW;
    const unsigned* adjB = g_adjbits + (size_t)(rAg + 8)*NW;

    for (int t = 0; t < NT; t++) {
        CP_WAIT1;
        __syncthreads();
        const unsigned kb = sb + SOFF_K + (t & 1)*32768;
        const unsigned vb = sb + SOFF_V + (t & 1)*65536;

        float s[16][4];
#pragma unroll
        for (int j = 0; j < 16; j++)
#pragma unroll
            for (int q = 0; q < 4; q++) s[j][q] = 0.f;

        unsigned mA0 = adjA[t*4+0], mA1 = adjA[t*4+1], mA2 = adjA[t*4+2], mA3 = adjA[t*4+3];
        unsigned mB0 = adjB[t*4+0], mB1 = adjB[t*4+1], mB2 = adjB[t*4+2], mB3 = adjB[t*4+3];
        unsigned p1lo[16], p1hi[16], p2lo[16], p2hi[16];

        // softmax for one n8-chunk j: mask + exp + bf16 split
        auto softmax_j = [&](int j) {
            unsigned wa = (j < 4) ? mA0 : (j < 8) ? mA1 : (j < 12) ? mA2 : mA3;
            unsigned wb = (j < 4) ? mB0 : (j < 8) ? mB1 : (j < 12) ? mB2 : mB3;
            int bp = 8*(j & 3) + 2*(lane & 3);
            float pa0 = ((wa >> bp)     & 1u) ? ex2f(fmaf(s[j][0], LOG2E, -EXPC)) : 0.f;
            float pa1 = ((wa >> (bp+1)) & 1u) ? ex2f(fmaf(s[j][1], LOG2E, -EXPC)) : 0.f;
            float pb0 = ((wb >> bp)     & 1u) ? ex2f(fmaf(s[j][2], LOG2E, -EXPC)) : 0.f;
            float pb1 = ((wb >> (bp+1)) & 1u) ? ex2f(fmaf(s[j][3], LOG2E, -EXPC)) : 0.f;
            lA += pa0 + pa1;
            lB += pb0 + pb1;
            split2(pa0, pa1, p1lo[j], p2lo[j]);
            split2(pb0, pb1, p1hi[j], p2hi[j]);
        };
        // PV body for one 16-key chunk kk
        auto pv_kk = [&](int kk) {
            unsigned vx = ((2*kk + kv_sel) ^ kv_x7) << 4;
            unsigned a10 = p1lo[2*kk], a11 = p1hi[2*kk], a12 = p1lo[2*kk+1], a13 = p1hi[2*kk+1];
            unsigned a20 = p2lo[2*kk], a21 = p2hi[2*kk], a22 = p2lo[2*kk+1], a23 = p2hi[2*kk+1];
#pragma unroll
            for (int jp = 0; jp < 8; jp++) {
                unsigned bf[4];
                unsigned va = vb + kv_r*256 + jp*4096 + vx;
                ldsm4(bf, va);                        // V1 (rows = dout, pre-transposed)
                mma16816(o[2*jp],   a10,a11,a12,a13, bf[0],bf[1]);
                mma16816(o[2*jp+1], a10,a11,a12,a13, bf[2],bf[3]);
                mma16816(o[2*jp],   a20,a21,a22,a23, bf[0],bf[1]);
                mma16816(o[2*jp+1], a20,a21,a22,a23, bf[2],bf[3]);
                ldsm4(bf, va + 32768);                // V2
                mma16816(o[2*jp],   a10,a11,a12,a13, bf[0],bf[1]);
                mma16816(o[2*jp+1], a10,a11,a12,a13, bf[2],bf[3]);
            }
        };

        // ---- QK half 0: key chunks jp 0..3 (all dh) ----
#pragma unroll
        for (int kk = 0; kk < 4; kk++) {
            unsigned a1[4], a2[4];
            unsigned qx = ((2*kk + q_sel) ^ q_x7) << 4;
            ldsm4(a1, sQrow + qx);
            ldsm4(a2, sQrow + 16384 + qx);
            unsigned kx = ((2*kk + kv_sel) ^ kv_x7) << 4;
#pragma unroll
            for (int jp = 0; jp < 4; jp++) {
                unsigned bf[4];
                unsigned ka = kb + kv_r*128 + jp*2048 + kx;
                ldsm4(bf, ka);                        // K1
                mma16816(s[2*jp],   a1[0],a1[1],a1[2],a1[3], bf[0],bf[1]);
                mma16816(s[2*jp+1], a1[0],a1[1],a1[2],a1[3], bf[2],bf[3]);
                mma16816(s[2*jp],   a2[0],a2[1],a2[2],a2[3], bf[0],bf[1]);
                mma16816(s[2*jp+1], a2[0],a2[1],a2[2],a2[3], bf[2],bf[3]);
                ldsm4(bf, ka + 16384);                // K2
                mma16816(s[2*jp],   a1[0],a1[1],a1[2],a1[3], bf[0],bf[1]);
                mma16816(s[2*jp+1], a1[0],a1[1],a1[2],a1[3], bf[2],bf[3]);
            }
        }
        // ---- QK half 1 (jp 4..7) interleaved with softmax of half 0 ----
#pragma unroll
        for (int kk = 0; kk < 4; kk++) {
            unsigned a1[4], a2[4];
            unsigned qx = ((2*kk + q_sel) ^ q_x7) << 4;
            ldsm4(a1, sQrow + qx);
            ldsm4(a2, sQrow + 16384 + qx);
            unsigned kx = ((2*kk + kv_sel) ^ kv_x7) << 4;
#pragma unroll
            for (int jp = 4; jp < 8; jp++) {
                unsigned bf[4];
                unsigned ka = kb + kv_r*128 + jp*2048 + kx;
                ldsm4(bf, ka);
                mma16816(s[2*jp],   a1[0],a1[1],a1[2],a1[3], bf[0],bf[1]);
                mma16816(s[2*jp+1], a1[0],a1[1],a1[2],a1[3], bf[2],bf[3]);
                mma16816(s[2*jp],   a2[0],a2[1],a2[2],a2[3], bf[0],bf[1]);
                mma16816(s[2*jp+1], a2[0],a2[1],a2[2],a2[3], bf[2],bf[3]);
                ldsm4(bf, ka + 16384);
                mma16816(s[2*jp],   a1[0],a1[1],a1[2],a1[3], bf[0],bf[1]);
                mma16816(s[2*jp+1], a1[0],a1[1],a1[2],a1[3], bf[2],bf[3]);
            }
            softmax_j(2*kk);
            softmax_j(2*kk + 1);
        }
        // ---- PV half 0 (keys 0..63) interleaved with softmax of half 1 ----
#pragma unroll
        for (int kk = 0; kk < 4; kk++) {
            softmax_j(8 + 2*kk);
            softmax_j(9 + 2*kk);
            pv_kk(kk);
        }
        // ---- PV half 1 (keys 64..127) ----
#pragma unroll
        for (int kk = 4; kk < 8; kk++) pv_kk(kk);

        __syncthreads();   // everyone done reading buf (t&1) before overwrite
        if (t + 2 < NT) {
            size_t kx = ((size_t)b*NT + t + 2);
            unsigned kd = sb + SOFF_K + (t & 1)*32768;
            unsigned vd = sb + SOFF_V + (t & 1)*65536;
            cpcopy(kd,          (const char*)(g_K1 + kx*8192),  16384, tid);
            cpcopy(kd + 16384,  (const char*)(g_K2 + kx*8192),  16384, tid);
            cpcopy(vd,          (const char*)(g_V1 + kx*16384), 32768, tid);
            cpcopy(vd + 32768,  (const char*)(g_V2 + kx*16384), 32768, tid);
        }
        CP_COMMIT;
    }

    // ---- epilogue: quad-reduce l, normalize, store ----
    lA += __shfl_xor_sync(0xffffffffu, lA, 1);
    lA += __shfl_xor_sync(0xffffffffu, lA, 2);
    lB += __shfl_xor_sync(0xffffffffu, lB, 1);
    lB += __shfl_xor_sync(0xffffffffu, lB, 2);
    float invA = 1.f / lA, invB = 1.f / lB;

    float* outA = out + ((size_t)b*N_ + rAg)*DO + 2*(lane & 3);
    float* outB = outA + 8*DO;
#pragma unroll
    for (int j = 0; j < 16; j++) {
        *(float2*)(outA + 8*j) = make_float2(o[j][0]*invA, o[j][1]*invA);
        *(float2*)(outB + 8*j) = make_float2(o[j][2]*invB, o[j][3]*invB);
    }
}

// ---------------- launch ----------------
extern "C" void kernel_launch(void* const* d_in, const int* in_sizes, int n_in,
                              void* d_out, int out_size) {
    const float* h   = (const float*)d_in[0];
    const int*   adj = (const int*)  d_in[1];
    const float* Ws  = (const float*)d_in[2];
    const float* Wt  = (const float*)d_in[3];
    const float* Wc  = (const float*)d_in[4];
    float* out = (float*)d_out;

    cudaFuncSetAttribute(gat_proj_pack,
                         cudaFuncAttributeMaxDynamicSharedMemorySize, PP_SMEM);
    cudaFuncSetAttribute(gat_attn_kernel,
                         cudaFuncAttributeMaxDynamicSharedMemorySize, SMEM_TOT);

    // fork a non-blocking stream so the DRAM-bound adjacency pack overlaps the
    // LDS/issue-bound projection kernel. Event fork/join is graph-capturable.
    cudaStream_t s2;
    cudaEvent_t evFork, evJoin;
    cudaStreamCreateWithFlags(&s2, cudaStreamNonBlocking);
    cudaEventCreateWithFlags(&evFork, cudaEventDisableTiming);
    cudaEventCreateWithFlags(&evJoin, cudaEventDisableTiming);

    cudaEventRecord(evFork, 0);
    cudaStreamWaitEvent(s2, evFork, 0);

    gat_proj_pack<<<dim3(NT, B_, 2), 256, PP_SMEM>>>(h, Ws, Wt, Wc);   // stream 0
    gat_pack_adj_kernel<<<N_, 128, 0, s2>>>(adj);                      // stream s2

    cudaEventRecord(evJoin, s2);
    cudaStreamWaitEvent(0, evJoin, 0);

    gat_attn_kernel<<<dim3(N_/TM, B_), 256, SMEM_TOT>>>(out);          // stream 0

    cudaEventDestroy(evFork);
    cudaEventDestroy(evJoin);
    cudaStreamDestroy(s2);
}